// round 11
// baseline (speedup 1.0000x reference)
#include <cuda_runtime.h>
#include <cstdint>
#include <cfloat>

// Problem constants
#define F 4096      // nb_features
#define C 64        // coord dim
#define B 1024      // batch
#define K 16        // nb_neighbors
#define J (F*K + 1) // 65537 gathered columns

// Scratch (no allocations allowed; __device__ globals are the sanctioned path)
__device__ float g_sq[F];
__device__ int   g_cols[J];
__device__ float g_d2[(size_t)F * F];   // 64 MB distance-squared matrix (L2-resident)

__device__ __forceinline__ bool lexlt(float d, int g, float v, int i) {
    return (d < v) || (d == v && g < i);
}

__device__ __forceinline__ unsigned long long fma2p(unsigned long long a,
                                                    unsigned long long b,
                                                    unsigned long long c) {
    unsigned long long d;
    asm("fma.rn.f32x2 %0, %1, %2, %3;" : "=l"(d) : "l"(a), "l"(b), "l"(c));
    return d;
}
__device__ __forceinline__ float lo32(unsigned long long v) {
    return __uint_as_float((unsigned)v);
}
__device__ __forceinline__ float hi32(unsigned long long v) {
    return __uint_as_float((unsigned)(v >> 32));
}

// ---------------------------------------------------------------------------
// Kernel 1: per-feature squared norms (UNFUSED mul+add, sequential — matches
// the reference's square+reduce rounding; rel_err is exactly 0 with this).
// ---------------------------------------------------------------------------
__global__ __launch_bounds__(256) void k_sq(const float* __restrict__ coord) {
    int f = blockIdx.x * 256 + threadIdx.x;
    float s = 0.f;
#pragma unroll
    for (int c = 0; c < C; ++c) {
        float x = coord[c * F + f];
        s = __fadd_rn(s, __fmul_rn(x, x));
    }
    g_sq[f] = s;
}

// ---------------------------------------------------------------------------
// Kernel 2: PURE distance GEMM -> g_d2 (verified ~52-59us; unchanged).
// ---------------------------------------------------------------------------
#define ROWS_CTA 32
#define GW       1024
#define TGG      128
#define NT       (GW / TGG)   // 8

__global__ __launch_bounds__(256) void k_dist(const float* __restrict__ coord) {
    __shared__ float s_f[C * ROWS_CTA];   // 8 KB
    __shared__ float s_sqf[ROWS_CTA];
    __shared__ float s_g[C * TGG];        // 32 KB
    __shared__ float s_sqg[TGG];

    const int tid  = threadIdx.x;
    const int lane = tid & 31;
    const int w    = tid >> 5;           // warp id: rows w*4 .. w*4+3
    const int f0   = (blockIdx.x >> 2) * ROWS_CTA;
    const int g0   = (blockIdx.x & 3) * GW;

    for (int idx = tid; idx < (C * ROWS_CTA) / 4; idx += 256) {
        int c = idx >> 3, r4 = (idx & 7) * 4;
        *(float4*)(s_f + c * ROWS_CTA + r4) = *(const float4*)(coord + c * F + f0 + r4);
    }
    if (tid < ROWS_CTA / 4)
        *(float4*)(s_sqf + tid * 4) = *(const float4*)(g_sq + f0 + tid * 4);

    for (int t = 0; t < NT; ++t) {
        const int gb = g0 + t * TGG;
        __syncthreads();
        for (int idx = tid; idx < (C * TGG) / 4; idx += 256) {
            int c = idx >> 5, o4 = (idx & 31) * 4;
            *(float4*)(s_g + c * TGG + o4) = *(const float4*)(coord + c * F + gb + o4);
        }
        if (tid < TGG / 4)
            *(float4*)(s_sqg + tid * 4) = *(const float4*)(g_sq + gb + tid * 4);
        __syncthreads();

        unsigned long long p00 = 0, p01 = 0, p10 = 0, p11 = 0;
        unsigned long long p20 = 0, p21 = 0, p30 = 0, p31 = 0;

        const float* fp = s_f + w * 4;
        const float* gp = s_g + lane * 4;
#pragma unroll 2
        for (int c = 0; c < C; ++c) {
            float4 a = *(const float4*)(fp + c * ROWS_CTA);            // 4 rows, bcast
            ulonglong2 bb = *(const ulonglong2*)(gp + c * TGG);        // g pairs
            unsigned long long ax, ay, az, aw;
            asm("mov.b64 %0,{%1,%1};" : "=l"(ax) : "r"(__float_as_uint(a.x)));
            asm("mov.b64 %0,{%1,%1};" : "=l"(ay) : "r"(__float_as_uint(a.y)));
            asm("mov.b64 %0,{%1,%1};" : "=l"(az) : "r"(__float_as_uint(a.z)));
            asm("mov.b64 %0,{%1,%1};" : "=l"(aw) : "r"(__float_as_uint(a.w)));
            p00 = fma2p(ax, bb.x, p00);  p01 = fma2p(ax, bb.y, p01);
            p10 = fma2p(ay, bb.x, p10);  p11 = fma2p(ay, bb.y, p11);
            p20 = fma2p(az, bb.x, p20);  p21 = fma2p(az, bb.y, p21);
            p30 = fma2p(aw, bb.x, p30);  p31 = fma2p(aw, bb.y, p31);
        }

        float4 sg = *(const float4*)(s_sqg + lane * 4);
        const float* sfp = s_sqf + w * 4;
        float* obase = g_d2 + (size_t)(f0 + w * 4) * F + gb + lane * 4;
#define FIN_ROW(PL, PH, R)                                                     \
        {                                                                      \
            float sf = sfp[R];                                                 \
            float4 d;                                                          \
            d.x = __fadd_rn(__fmaf_rn(-2.f, lo32(PL), sg.x), sf);              \
            d.y = __fadd_rn(__fmaf_rn(-2.f, hi32(PL), sg.y), sf);              \
            d.z = __fadd_rn(__fmaf_rn(-2.f, lo32(PH), sg.z), sf);              \
            d.w = __fadd_rn(__fmaf_rn(-2.f, hi32(PH), sg.w), sf);              \
            *(float4*)(obase + (size_t)(R) * F) = d;                           \
        }
        FIN_ROW(p00, p01, 0) FIN_ROW(p10, p11, 1)
        FIN_ROW(p20, p21, 2) FIN_ROW(p30, p31, 3)
#undef FIN_ROW
    }
}

// ---------------------------------------------------------------------------
// Kernel 3: per-row top-16. Atomic-free 5-bit ballot radix select, now
// LATENCY-FIXED: float4 loads (MLP 4x) + min/max pre-pass that skips the
// single-bin leading passes (seeds prefix with the shared high bits).
// One warp per row; 512 CTAs x 8 warps.
// ---------------------------------------------------------------------------
#define SEL_WARPS 8
#define CANDMAX   128

__global__ __launch_bounds__(256) void k_select() {
    __shared__ int   cand[SEL_WARPS][CANDMAX];
    __shared__ float cd[SEL_WARPS][CANDMAX];

    const int w    = threadIdx.x >> 5;
    const int lane = threadIdx.x & 31;
    const int row  = blockIdx.x * SEL_WARPS + w;
    const float* dr = g_d2 + (size_t)row * F;

    // --- pre-pass: row min/max of clamped keys (float4, cheap) ---
    float fmn = FLT_MAX, fmx = 0.f;
#pragma unroll 2
    for (int it = 0; it < F / 128; ++it) {
        float4 v = *(const float4*)(dr + it * 128 + lane * 4);
        float a = fmaxf(v.x, 0.f), b = fmaxf(v.y, 0.f);
        float c = fmaxf(v.z, 0.f), d = fmaxf(v.w, 0.f);
        fmn = fminf(fmn, fminf(fminf(a, b), fminf(c, d)));
        fmx = fmaxf(fmx, fmaxf(fmaxf(a, b), fmaxf(c, d)));
    }
#pragma unroll
    for (int s = 16; s >= 1; s >>= 1) {
        fmn = fminf(fmn, __shfl_xor_sync(0xFFFFFFFFu, fmn, s));
        fmx = fmaxf(fmx, __shfl_xor_sync(0xFFFFFFFFu, fmx, s));
    }
    unsigned umin = __float_as_uint(fmn), umax = __float_as_uint(fmx);
    unsigned diff = umin ^ umax;
    // first differing 5-bit window on the grid {27,22,17,12,7,2}
    int h = (diff == 0u) ? 2 : (31 - __clz(diff));
    int p0i = (31 - h) / 5;            // 0..5
    if (p0i > 5) p0i = 5;
    int start_shift = 27 - 5 * p0i;
    unsigned prefix = (start_shift == 27) ? 0u : (umax >> (start_shift + 5));

    // --- radix select: keys u = bits of fmaxf(d2,0) are bit-monotone ---
    int k = 16;       // rank within current prefix region
    int shift = start_shift;
    for (; shift >= 2; shift -= 5) {
        unsigned cntb = 0;   // count for bin `lane`
#pragma unroll 2
        for (int it = 0; it < F / 128; ++it) {
            float4 v = *(const float4*)(dr + it * 128 + lane * 4);
#define HIST_ELEM(VAL)                                                         \
            {                                                                  \
                unsigned u = __float_as_uint(fmaxf((VAL), 0.f));               \
                bool valid = (shift == 27) || ((u >> (shift + 5)) == prefix);  \
                unsigned digit = (u >> shift) & 31u;                           \
                unsigned V  = __ballot_sync(0xFFFFFFFFu, valid);               \
                unsigned B0 = __ballot_sync(0xFFFFFFFFu, digit & 1u);          \
                unsigned B1 = __ballot_sync(0xFFFFFFFFu, digit & 2u);          \
                unsigned B2 = __ballot_sync(0xFFFFFFFFu, digit & 4u);          \
                unsigned B3 = __ballot_sync(0xFFFFFFFFu, digit & 8u);          \
                unsigned B4 = __ballot_sync(0xFFFFFFFFu, digit & 16u);         \
                unsigned m = V;                                                \
                m &= (lane & 1)  ? B0 : ~B0;                                   \
                m &= (lane & 2)  ? B1 : ~B1;                                   \
                m &= (lane & 4)  ? B2 : ~B2;                                   \
                m &= (lane & 8)  ? B3 : ~B3;                                   \
                m &= (lane & 16) ? B4 : ~B4;                                   \
                cntb += __popc(m);                                             \
            }
            HIST_ELEM(v.x) HIST_ELEM(v.y) HIST_ELEM(v.z) HIST_ELEM(v.w)
#undef HIST_ELEM
        }
        // warp inclusive scan of per-bin counts (bin index = lane, ascending)
        int incl = (int)cntb;
#pragma unroll
        for (int d = 1; d < 32; d <<= 1) {
            int tt = __shfl_up_sync(0xFFFFFFFFu, incl, d);
            if (lane >= d) incl += tt;
        }
        int excl = incl - (int)cntb;
        bool has = (excl < k) && (k <= incl);
        unsigned bal = __ballot_sync(0xFFFFFFFFu, has);
        int src = __ffs(bal) - 1;                 // bin containing rank k
        int newk = __shfl_sync(0xFFFFFFFFu, k - excl, src);
        int bcnt = __shfl_sync(0xFFFFFFFFu, (int)cntb, src);
        prefix = (prefix << 5) | (unsigned)src;
        k = newk;
        // (16 - k) elements strictly below the bin; survivors ~ below + bcnt
        if ((16 - k) + bcnt <= CANDMAX - 8) { shift -= 5; break; }
    }
    shift += 5;   // shift of the last executed pass

    // threshold: end of the chosen bin, +7 ulp margin (covers sqrt-round ties)
    unsigned long long t64 = (((unsigned long long)prefix + 1ull) << shift) + 7ull;
    unsigned thr = (t64 > 0xFFFFFFFFull) ? 0xFFFFFFFFu : (unsigned)t64;

    // --- ballot compaction of survivors (order arbitrary; ranks fix it) ---
    int cnt = 0;
#pragma unroll 2
    for (int it = 0; it < F / 128; ++it) {
        float4 v = *(const float4*)(dr + it * 128 + lane * 4);
#define COMP_ELEM(VAL, E)                                                      \
        {                                                                      \
            float cv = fmaxf((VAL), 0.f);                                      \
            unsigned u = __float_as_uint(cv);                                  \
            bool take = (u <= thr);                                            \
            unsigned m = __ballot_sync(0xFFFFFFFFu, take);                     \
            int pos = cnt + __popc(m & ((1u << lane) - 1u));                   \
            if (take && pos < CANDMAX) {                                       \
                cand[w][pos] = it * 128 + lane * 4 + (E);                      \
                cd[w][pos]   = sqrtf(cv);                                      \
            }                                                                  \
            cnt += __popc(m);                                                  \
        }
        COMP_ELEM(v.x, 0) COMP_ELEM(v.y, 1) COMP_ELEM(v.z, 2) COMP_ELEM(v.w, 3)
#undef COMP_ELEM
    }
    if (cnt > CANDMAX) cnt = CANDMAX;
    __syncwarp();

    // --- exact lex (d, idx) ranks in parallel; ranks are a permutation ---
#pragma unroll
    for (int q = lane; q < CANDMAX; q += 32) {
        if (q < cnt) {
            float dq = cd[w][q]; int gq = cand[w][q];
            int rank = 0;
            for (int j = 0; j < cnt; ++j) {
                rank += lexlt(cd[w][j], cand[w][j], dq, gq) ? 1 : 0;
            }
            if (rank < K) g_cols[1 + row * K + rank] = gq;
        }
    }
    if (row == 0 && lane == 0) g_cols[0] = 0;
}

// ---------------------------------------------------------------------------
// Kernel 4: gather. RB=2 rows/CTA (32 KB smem -> higher occupancy, 512 CTAs),
// scalar streaming stores (the proven-fast store path).
// ---------------------------------------------------------------------------
#define RB 2
#define GATHER_SMEM (RB * F * 4)

__global__ __launch_bounds__(256) void k_gather(const float* __restrict__ inputs,
                                                float* __restrict__ out) {
    extern __shared__ float s_in[];   // RB * 4096
    const int b0 = blockIdx.x * RB;

    for (int idx = threadIdx.x; idx < (RB * F) / 4; idx += 256) {
        int r = idx >> 10, q = idx & 1023;
        *(float4*)(s_in + r * F + q * 4) =
            *(const float4*)(inputs + (size_t)(b0 + r) * F + q * 4);
    }
    __syncthreads();

    for (int j = threadIdx.x; j < J; j += 256) {
        int c = __ldg(&g_cols[j]);
#pragma unroll
        for (int r = 0; r < RB; ++r) {
            __stcs(out + (size_t)(b0 + r) * J + j, s_in[r * F + c]);
        }
    }
}

// ---------------------------------------------------------------------------
extern "C" void kernel_launch(void* const* d_in, const int* in_sizes, int n_in,
                              void* d_out, int out_size) {
    const float* inputs = (const float*)d_in[0];
    const float* coord  = (const float*)d_in[1];
    if (n_in >= 2 && in_sizes[0] < in_sizes[1]) {
        const float* t = inputs; inputs = coord; coord = t;
    }
    float* out = (float*)d_out;

    static bool attr_done = false;
    if (!attr_done) {
        cudaFuncSetAttribute(k_gather, cudaFuncAttributeMaxDynamicSharedMemorySize,
                             GATHER_SMEM);
        attr_done = true;
    }

    k_sq<<<F / 256, 256>>>(coord);
    k_dist<<<(F / ROWS_CTA) * (F / GW), 256>>>(coord);
    k_select<<<F / SEL_WARPS, 256>>>();
    k_gather<<<B / RB, 256, GATHER_SMEM>>>(inputs, out);
}

// round 12
// speedup vs baseline: 1.4858x; 1.4858x over previous
#include <cuda_runtime.h>
#include <cstdint>
#include <cfloat>

// Problem constants
#define F 4096      // nb_features
#define C 64        // coord dim
#define B 1024      // batch
#define K 16        // nb_neighbors
#define J (F*K + 1) // 65537 gathered columns

// Scratch (no allocations allowed; __device__ globals are the sanctioned path)
__device__ float g_sq[F];
__device__ int   g_cols[J];
__device__ float g_d2[(size_t)F * F];   // 64 MB distance-squared matrix (L2-resident)

__device__ __forceinline__ bool lexlt(float d, int g, float v, int i) {
    return (d < v) || (d == v && g < i);
}

__device__ __forceinline__ unsigned long long fma2p(unsigned long long a,
                                                    unsigned long long b,
                                                    unsigned long long c) {
    unsigned long long d;
    asm("fma.rn.f32x2 %0, %1, %2, %3;" : "=l"(d) : "l"(a), "l"(b), "l"(c));
    return d;
}
__device__ __forceinline__ float lo32(unsigned long long v) {
    return __uint_as_float((unsigned)v);
}
__device__ __forceinline__ float hi32(unsigned long long v) {
    return __uint_as_float((unsigned)(v >> 32));
}

// ---------------------------------------------------------------------------
// Kernel 1: per-feature squared norms (UNFUSED mul+add, sequential — matches
// the reference's square+reduce rounding; rel_err is exactly 0 with this).
// ---------------------------------------------------------------------------
__global__ __launch_bounds__(256) void k_sq(const float* __restrict__ coord) {
    int f = blockIdx.x * 256 + threadIdx.x;
    float s = 0.f;
#pragma unroll
    for (int c = 0; c < C; ++c) {
        float x = coord[c * F + f];
        s = __fadd_rn(s, __fmul_rn(x, x));
    }
    g_sq[f] = s;
}

// ---------------------------------------------------------------------------
// Kernel 2: PURE distance GEMM -> g_d2 (verified ~52us; unchanged).
// ---------------------------------------------------------------------------
#define ROWS_CTA 32
#define GW       1024
#define TGG      128
#define NT       (GW / TGG)   // 8

__global__ __launch_bounds__(256) void k_dist(const float* __restrict__ coord) {
    __shared__ float s_f[C * ROWS_CTA];   // 8 KB
    __shared__ float s_sqf[ROWS_CTA];
    __shared__ float s_g[C * TGG];        // 32 KB
    __shared__ float s_sqg[TGG];

    const int tid  = threadIdx.x;
    const int lane = tid & 31;
    const int w    = tid >> 5;           // warp id: rows w*4 .. w*4+3
    const int f0   = (blockIdx.x >> 2) * ROWS_CTA;
    const int g0   = (blockIdx.x & 3) * GW;

    for (int idx = tid; idx < (C * ROWS_CTA) / 4; idx += 256) {
        int c = idx >> 3, r4 = (idx & 7) * 4;
        *(float4*)(s_f + c * ROWS_CTA + r4) = *(const float4*)(coord + c * F + f0 + r4);
    }
    if (tid < ROWS_CTA / 4)
        *(float4*)(s_sqf + tid * 4) = *(const float4*)(g_sq + f0 + tid * 4);

    for (int t = 0; t < NT; ++t) {
        const int gb = g0 + t * TGG;
        __syncthreads();
        for (int idx = tid; idx < (C * TGG) / 4; idx += 256) {
            int c = idx >> 5, o4 = (idx & 31) * 4;
            *(float4*)(s_g + c * TGG + o4) = *(const float4*)(coord + c * F + gb + o4);
        }
        if (tid < TGG / 4)
            *(float4*)(s_sqg + tid * 4) = *(const float4*)(g_sq + gb + tid * 4);
        __syncthreads();

        unsigned long long p00 = 0, p01 = 0, p10 = 0, p11 = 0;
        unsigned long long p20 = 0, p21 = 0, p30 = 0, p31 = 0;

        const float* fp = s_f + w * 4;
        const float* gp = s_g + lane * 4;
#pragma unroll 2
        for (int c = 0; c < C; ++c) {
            float4 a = *(const float4*)(fp + c * ROWS_CTA);            // 4 rows, bcast
            ulonglong2 bb = *(const ulonglong2*)(gp + c * TGG);        // g pairs
            unsigned long long ax, ay, az, aw;
            asm("mov.b64 %0,{%1,%1};" : "=l"(ax) : "r"(__float_as_uint(a.x)));
            asm("mov.b64 %0,{%1,%1};" : "=l"(ay) : "r"(__float_as_uint(a.y)));
            asm("mov.b64 %0,{%1,%1};" : "=l"(az) : "r"(__float_as_uint(a.z)));
            asm("mov.b64 %0,{%1,%1};" : "=l"(aw) : "r"(__float_as_uint(a.w)));
            p00 = fma2p(ax, bb.x, p00);  p01 = fma2p(ax, bb.y, p01);
            p10 = fma2p(ay, bb.x, p10);  p11 = fma2p(ay, bb.y, p11);
            p20 = fma2p(az, bb.x, p20);  p21 = fma2p(az, bb.y, p21);
            p30 = fma2p(aw, bb.x, p30);  p31 = fma2p(aw, bb.y, p31);
        }

        float4 sg = *(const float4*)(s_sqg + lane * 4);
        const float* sfp = s_sqf + w * 4;
        float* obase = g_d2 + (size_t)(f0 + w * 4) * F + gb + lane * 4;
#define FIN_ROW(PL, PH, R)                                                     \
        {                                                                      \
            float sf = sfp[R];                                                 \
            float4 d;                                                          \
            d.x = __fadd_rn(__fmaf_rn(-2.f, lo32(PL), sg.x), sf);              \
            d.y = __fadd_rn(__fmaf_rn(-2.f, hi32(PL), sg.y), sf);              \
            d.z = __fadd_rn(__fmaf_rn(-2.f, lo32(PH), sg.z), sf);              \
            d.w = __fadd_rn(__fmaf_rn(-2.f, hi32(PH), sg.w), sf);              \
            *(float4*)(obase + (size_t)(R) * F) = d;                           \
        }
        FIN_ROW(p00, p01, 0) FIN_ROW(p10, p11, 1)
        FIN_ROW(p20, p21, 2) FIN_ROW(p30, p31, 3)
#undef FIN_ROW
    }
}

// ---------------------------------------------------------------------------
// Kernel 3: per-row top-16 via CTA-wide BISECTION on the bit-monotone key of
// fmaxf(d2,0). No ballots, no histograms: each thread holds 16 row elements
// in registers; each bisection step is 16 compare-adds + one redux.sync +
// block sum. Exact 16th key found (bracket collapse), +7 ulp sqrt-tie margin,
// smem compaction (order-free), then exact (sqrt, idx) lex ranks in parallel.
// One CTA (256 threads) per row.
// ---------------------------------------------------------------------------
#define ELEMS   16              // F / 256
#define CANDMAX 128

__global__ __launch_bounds__(256) void k_select() {
    __shared__ unsigned s_mn[8], s_mx[8];
    __shared__ int s_red[8];
    __shared__ int s_cnt;
    __shared__ int s_pos;
    __shared__ int   cand[CANDMAX];
    __shared__ float cdv[CANDMAX];

    const int t   = threadIdx.x;
    const int row = blockIdx.x;
    const float* dr = g_d2 + (size_t)row * F;

    // registers: element i of thread t is row index i*256 + t (coalesced)
    unsigned u[ELEMS];
#pragma unroll
    for (int i = 0; i < ELEMS; ++i)
        u[i] = __float_as_uint(fmaxf(dr[i * 256 + t], 0.f));

    // --- block min/max of keys ---
    unsigned mn = 0xFFFFFFFFu, mx = 0u;
#pragma unroll
    for (int i = 0; i < ELEMS; ++i) { mn = min(mn, u[i]); mx = max(mx, u[i]); }
    mn = __reduce_min_sync(0xFFFFFFFFu, mn);
    mx = __reduce_max_sync(0xFFFFFFFFu, mx);
    if ((t & 31) == 0) { s_mn[t >> 5] = mn; s_mx[t >> 5] = mx; }
    __syncthreads();
    unsigned lo = s_mn[0], hi = s_mx[0];
#pragma unroll
    for (int j = 1; j < 8; ++j) { lo = min(lo, s_mn[j]); hi = max(hi, s_mx[j]); }

    // --- bisection: smallest key T with count(u <= T) >= K ---
    // invariant: count(u <= hi) >= K; chi tracks count(u <= hi)
    int chi = F;
    while (chi > 96 && lo < hi) {
        unsigned mid = lo + ((hi - lo) >> 1);
        int lc = 0;
#pragma unroll
        for (int i = 0; i < ELEMS; ++i) lc += (u[i] <= mid) ? 1 : 0;
        lc = __reduce_add_sync(0xFFFFFFFFu, lc);
        if ((t & 31) == 0) s_red[t >> 5] = lc;
        __syncthreads();
        if (t == 0) {
            int c = 0;
#pragma unroll
            for (int j = 0; j < 8; ++j) c += s_red[j];
            s_cnt = c;
        }
        __syncthreads();
        int c = s_cnt;
        if (c >= K) { hi = mid; chi = c; } else { lo = mid + 1; }
        // s_red rewrite next iter is safe: everyone passed the sync after
        // t0 consumed s_red.
    }

    // threshold: exact-or-bracketed 16th key, +7 ulp margin (sqrt-round ties)
    unsigned long long t64 = (unsigned long long)hi + 7ull;
    unsigned thr = (t64 > 0xFFFFFFFFull) ? 0xFFFFFFFFu : (unsigned)t64;

    // --- compaction (order arbitrary; ranks are order-independent) ---
    if (t == 0) s_pos = 0;
    __syncthreads();
#pragma unroll
    for (int i = 0; i < ELEMS; ++i) {
        if (u[i] <= thr) {
            int p = atomicAdd_block(&s_pos, 1);
            if (p < CANDMAX) {
                cand[p] = i * 256 + t;
                cdv[p]  = sqrtf(__uint_as_float(u[i]));
            }
        }
    }
    __syncthreads();
    int cnt = s_pos < CANDMAX ? s_pos : CANDMAX;

    // --- exact lex (d, idx) ranks in parallel; ranks are a permutation ---
    if (t < cnt) {
        float dq = cdv[t]; int gq = cand[t];
        int rank = 0;
        for (int j = 0; j < cnt; ++j) {
            rank += lexlt(cdv[j], cand[j], dq, gq) ? 1 : 0;
        }
        if (rank < K) g_cols[1 + row * K + rank] = gq;
    }
    if (row == 0 && t == 0) g_cols[0] = 0;
}

// ---------------------------------------------------------------------------
// Kernel 4: gather (frozen round-4/round-10 winner: RB=4, scalar __stcs).
// ---------------------------------------------------------------------------
#define RB 4
#define GATHER_SMEM (RB * F * 4)

__global__ __launch_bounds__(256) void k_gather(const float* __restrict__ inputs,
                                                float* __restrict__ out) {
    extern __shared__ float s_in[];   // RB * 4096
    const int b0 = blockIdx.x * RB;

    for (int idx = threadIdx.x; idx < (RB * F) / 4; idx += 256) {
        int r = idx >> 10, q = idx & 1023;
        *(float4*)(s_in + r * F + q * 4) =
            *(const float4*)(inputs + (size_t)(b0 + r) * F + q * 4);
    }
    __syncthreads();

    for (int j = threadIdx.x; j < J; j += 256) {
        int c = __ldg(&g_cols[j]);
#pragma unroll
        for (int r = 0; r < RB; ++r) {
            __stcs(out + (size_t)(b0 + r) * J + j, s_in[r * F + c]);
        }
    }
}

// ---------------------------------------------------------------------------
extern "C" void kernel_launch(void* const* d_in, const int* in_sizes, int n_in,
                              void* d_out, int out_size) {
    const float* inputs = (const float*)d_in[0];
    const float* coord  = (const float*)d_in[1];
    if (n_in >= 2 && in_sizes[0] < in_sizes[1]) {
        const float* t = inputs; inputs = coord; coord = t;
    }
    float* out = (float*)d_out;

    static bool attr_done = false;
    if (!attr_done) {
        cudaFuncSetAttribute(k_gather, cudaFuncAttributeMaxDynamicSharedMemorySize,
                             GATHER_SMEM);
        attr_done = true;
    }

    k_sq<<<F / 256, 256>>>(coord);
    k_dist<<<(F / ROWS_CTA) * (F / GW), 256>>>(coord);
    k_select<<<F, 256>>>();
    k_gather<<<B / RB, 256, GATHER_SMEM>>>(inputs, out);
}